// round 15
// baseline (speedup 1.0000x reference)
#include <cuda_runtime.h>
#include <cuda_bf16.h>
#include <cuda_fp16.h>
#include <cstdint>

// ---------------------------------------------------------------------------
// SPN neuron: B=32768, F=512, P=256 scope pairs, M=8 mixture components.
//
// Log2-domain quadratic form per (p,m):
//   t_m = A1*x1^2 + B1*x1 + A2*x2^2 + B2*x2 + C     (scaled by log2 e)
//   lse2 = mx + log2( sum_m 2^(t_m - mx) )
//   out[b] = ln(2) * sum_p lse2_p
//
// R14: R13 (36.9us: warp-parallel precompute + transposed smem reduction,
// regs 72, occ 3) + packed ex2.approx.f16x2 for the mixture exp. Ledger
// evidence: R9 vs R10 shows packed exp is ~4us FASTER in identical
// structure (the earlier "f16x2 regressed" verdict was the fused prologue's
// fault, not the packed math). MUFU ops/pair 9 -> 5; MUFU busy ~17.7 ->
// ~9.8us. Register headroom (72 -> ~85) absorbs the temporaries without
// spills now that acc[]/shuffle chains are gone.
// ---------------------------------------------------------------------------

#define LOG2E_F    1.4426950408889634f
#define LN2_F      0.6931471805599453f
#define LOG2_2PI_F 2.6514961294723187f   // log2(2*pi)

constexpr int PF   = 512;   // features
constexpr int PP   = 256;   // scope pairs
constexpr int PM   = 8;     // mixture components
constexpr int ROWS = 8;     // batch rows per chunk

__device__ float g_coef[5 * PM * PP];   // [j in 0..4][m][p], p fastest
__device__ int2  g_scope2[PP];          // per-pair (s0, s1)

__device__ __forceinline__ float lg2f(float v) {
    float r; asm("lg2.approx.ftz.f32 %0, %1;" : "=f"(r) : "f"(v)); return r;
}
__device__ __forceinline__ float rcpf(float v) {
    float r; asm("rcp.approx.ftz.f32 %0, %1;" : "=f"(r) : "f"(v)); return r;
}
// pack two f32 into f16x2 (order irrelevant: results get summed)
__device__ __forceinline__ unsigned cvt_f16x2(float a, float b) {
    unsigned r; asm("cvt.rn.f16x2.f32 %0, %1, %2;" : "=r"(r) : "f"(a), "f"(b));
    return r;
}
__device__ __forceinline__ unsigned ex2_h2(unsigned v) {
    unsigned r; asm("ex2.approx.f16x2 %0, %1;" : "=r"(r) : "r"(v)); return r;
}
__device__ __forceinline__ unsigned hadd2u(unsigned a, unsigned b) {
    unsigned r; asm("add.f16x2 %0, %1, %2;" : "=r"(r) : "r"(a), "r"(b));
    return r;
}
__device__ __forceinline__ float h2_total(unsigned v) {
    float lo, hi;
    asm("{ .reg .f16 l, h;\n\t"
        "  mov.b32 {l, h}, %2;\n\t"
        "  cvt.f32.f16 %0, l;\n\t"
        "  cvt.f32.f16 %1, h; }"
        : "=f"(lo), "=f"(hi) : "r"(v));
    return lo + hi;
}
__device__ __forceinline__ void cp16(uint32_t smem_dst, const void* gmem_src) {
    asm volatile("cp.async.cg.shared.global [%0], [%1], 16;\n"
                 :: "r"(smem_dst), "l"(gmem_src));
}
__device__ __forceinline__ void cp_commit() {
    asm volatile("cp.async.commit_group;\n" ::: "memory");
}
template <int N>
__device__ __forceinline__ void cp_wait() {
    asm volatile("cp.async.wait_group %0;\n" :: "n"(N) : "memory");
}

// ---------------------------------------------------------------------------
// Precompute: 256 blocks x 32 threads. Block p = scope pair p; lane m < 8
// computes component m's 5 coefficients. Fully parallel, no serial scans.
// ---------------------------------------------------------------------------
__global__ void spn_precompute_kernel(const float* __restrict__ mean,
                                      const float* __restrict__ stdv,
                                      const float* __restrict__ wts,
                                      const int*   __restrict__ w32)
{
    const int p    = blockIdx.x;
    const int lane = threadIdx.x;

    // dtype detection: int64 LE values in [0,512) have zero odd words; an
    // int32 permutation of 0..511 has at most ONE zero among words 1..63.
    unsigned odd = __ballot_sync(0xffffffffu, w32[2 * lane + 1] != 0);
    const bool is32 = (odd != 0);

    if (lane == 0) {
        int s0 = (is32 ? w32[2 * p] : w32[4 * p]) & (PF - 1);
        int s1 = (is32 ? w32[2 * p + 1] : w32[4 * p + 2]) & (PF - 1);
        g_scope2[p] = make_int2(s0, s1);
    }

    // weight sum across the 8 components (xor offsets 4,2,1 reduce within
    // 8-lane groups, so lanes 0..7 all hold the sum of lanes 0..7)
    float w = (lane < PM) ? wts[p * PM + lane] : 0.f;
    float wsum = w;
    #pragma unroll
    for (int off = 4; off; off >>= 1)
        wsum += __shfl_xor_sync(0xffffffffu, wsum, off);

    if (lane >= PM) return;
    const int m = lane;
    const float l2wsum = lg2f(wsum);

    int base = (p * PM + m) * 2;
    float mu1 = mean[base + 0], mu2 = mean[base + 1];
    float sd1 = stdv[base + 0], sd2 = stdv[base + 1];
    float r1 = rcpf(sd1), r2 = rcpf(sd2);
    float i1 = r1 * r1, i2 = r2 * r2;

    g_coef[(0 * PM + m) * PP + p] = -0.5f * i1 * LOG2E_F;
    g_coef[(1 * PM + m) * PP + p] =  mu1  * i1 * LOG2E_F;
    g_coef[(2 * PM + m) * PP + p] = -0.5f * i2 * LOG2E_F;
    g_coef[(3 * PM + m) * PP + p] =  mu2  * i2 * LOG2E_F;
    g_coef[(4 * PM + m) * PP + p] =
        -0.5f * LOG2E_F * (mu1 * mu1 * i1 + mu2 * mu2 * i2)
        - lg2f(sd1 * sd2) - LOG2_2PI_F + lg2f(w) - l2wsum;
}

// ---------------------------------------------------------------------------
// Main kernel: blockDim = 256 (thread == pair). Grid-stride over 8-row
// chunks, double-buffered cp.async staging, transposed smem reduction,
// packed f16x2 mixture exp.
// ---------------------------------------------------------------------------
__global__ __launch_bounds__(256, 2)
void spn_main_kernel(const float* __restrict__ x,
                     float* __restrict__ out,
                     int nchunks)
{
    __shared__ float sx[2][ROWS][PF];
    __shared__ float sred[ROWS][PP];   // [row][pair] transpose buffer

    const int tid  = threadIdx.x;
    const int lane = tid & 31;
    const int warp = tid >> 5;

    // Coefficients -> registers (coalesced: p is fastest dim of g_coef)
    float A1[PM], B1[PM], A2[PM], B2[PM], Cc[PM];
    #pragma unroll
    for (int m = 0; m < PM; m++) {
        A1[m] = g_coef[(0 * PM + m) * PP + tid];
        B1[m] = g_coef[(1 * PM + m) * PP + tid];
        A2[m] = g_coef[(2 * PM + m) * PP + tid];
        B2[m] = g_coef[(3 * PM + m) * PP + tid];
        Cc[m] = g_coef[(4 * PM + m) * PP + tid];
    }
    const int2 ss = g_scope2[tid];
    const int s0 = ss.x, s1 = ss.y;

    const int stride = gridDim.x;
    const uint32_t sbase = (uint32_t)__cvta_generic_to_shared(&sx[0][0][0]);

    // Prologue: stage first chunk into buffer 0.
    int c = blockIdx.x;
    if (c < nchunks) {
        const char* src = (const char*)(x + (size_t)c * ROWS * PF);
        #pragma unroll
        for (int k = 0; k < 4; k++)
            cp16(sbase + (tid + k * 256) * 16, src + (tid + k * 256) * 16);
    }
    cp_commit();

    int buf = 0;
    for (; c < nchunks; c += stride, buf ^= 1) {
        int cn = c + stride;
        if (cn < nchunks) {
            const char* src = (const char*)(x + (size_t)cn * ROWS * PF);
            uint32_t dst = sbase + (uint32_t)(buf ^ 1) * (ROWS * PF * 4);
            #pragma unroll
            for (int k = 0; k < 4; k++)
                cp16(dst + (tid + k * 256) * 16, src + (tid + k * 256) * 16);
        }
        cp_commit();
        cp_wait<1>();          // current chunk's group has landed
        __syncthreads();       // visible to all; prev iter's sred consumed

        #pragma unroll
        for (int r = 0; r < ROWS; r++) {
            float x1 = sx[buf][r][s0];
            float x2 = sx[buf][r][s1];
            float x1s = x1 * x1;
            float x2s = x2 * x2;

            float t[PM];
            #pragma unroll
            for (int m = 0; m < PM; m++) {
                float v = fmaf(B2[m], x2, Cc[m]);
                v = fmaf(A2[m], x2s, v);
                v = fmaf(B1[m], x1, v);
                v = fmaf(A1[m], x1s, v);
                t[m] = v;
            }
            float m01 = fmaxf(t[0], t[1]), m23 = fmaxf(t[2], t[3]);
            float m45 = fmaxf(t[4], t[5]), m67 = fmaxf(t[6], t[7]);
            float mx  = fmaxf(fmaxf(m01, m23), fmaxf(m45, m67));

            // packed exp: 4x ex2.f16x2 instead of 8x ex2.f32
            // (t - mx <= 0; very negative -> f16 -inf -> ex2 -> 0: correct)
            unsigned e0 = ex2_h2(cvt_f16x2(t[0] - mx, t[1] - mx));
            unsigned e1 = ex2_h2(cvt_f16x2(t[2] - mx, t[3] - mx));
            unsigned e2 = ex2_h2(cvt_f16x2(t[4] - mx, t[5] - mx));
            unsigned e3 = ex2_h2(cvt_f16x2(t[6] - mx, t[7] - mx));
            unsigned sh = hadd2u(hadd2u(e0, e1), hadd2u(e2, e3));

            // transpose store: lanes hit distinct banks (addr = r*256 + tid)
            sred[r][tid] = mx + lg2f(h2_total(sh));
        }
        __syncthreads();

        // Warp w sums row w over all 256 pairs: 8 stride-32 loads
        // (conflict-free) + tree add + 5-level shuffle. Uniform across warps.
        {
            float v0 = sred[warp][lane +   0] + sred[warp][lane +  32];
            float v1 = sred[warp][lane +  64] + sred[warp][lane +  96];
            float v2 = sred[warp][lane + 128] + sred[warp][lane + 160];
            float v3 = sred[warp][lane + 192] + sred[warp][lane + 224];
            float v  = (v0 + v1) + (v2 + v3);
            #pragma unroll
            for (int off = 16; off; off >>= 1)
                v += __shfl_xor_sync(0xffffffffu, v, off);
            if (lane == 0) out[c * ROWS + warp] = v * LN2_F;
        }
        // No trailing barrier: next iter's top barrier (after cp_wait) orders
        // this iter's sred reads against next iter's sred writes, and the
        // cp.async issued at next-iter top targets the buffer whose last
        // reads were sealed by this iteration's mid barrier.
    }
}

// ---------------------------------------------------------------------------
// Launch. Inputs: x f32[32768*512], mean f32[256*8*2], std f32[256*8*2],
// weights f32[256*8], scopes int{32,64}[512]. Output f32[32768].
// ---------------------------------------------------------------------------
extern "C" void kernel_launch(void* const* d_in, const int* in_sizes, int n_in,
                              void* d_out, int out_size)
{
    const float* x      = (const float*)d_in[0];
    const float* mean   = (const float*)d_in[1];
    const float* stdv   = (const float*)d_in[2];
    const float* wts    = (const float*)d_in[3];
    const int*   w32    = (const int*)d_in[4];
    float*       out    = (float*)d_out;

    const int B = in_sizes[0] / PF;          // 32768
    const int nchunks = B / ROWS;            // 4096

    spn_precompute_kernel<<<PP, 32>>>(mean, stdv, wts, w32);

    // Grid 1184: measured-best main-loop config.
    int blocks = 1184;
    if (blocks > nchunks) blocks = nchunks;
    spn_main_kernel<<<blocks, 256>>>(x, out, nchunks);
}

// round 16
// speedup vs baseline: 1.0886x; 1.0886x over previous
#include <cuda_runtime.h>
#include <cuda_bf16.h>
#include <cstdint>

// ---------------------------------------------------------------------------
// SPN neuron: B=32768, F=512, P=256 scope pairs, M=8 mixture components.
//
// Log2-domain quadratic form per (p,m):
//   t_m = A1*x1^2 + B1*x1 + A2*x2^2 + B2*x2 + C     (scaled by log2 e)
//   lse2 = mx + log2( sum_m 2^(t_m - mx) )
//   out[b] = ln(2) * sum_p lse2_p
//
// R15: R13 structure (36.9us best: warp-parallel precompute, transposed
// smem reduction, cp.async double buffer, grid 1184) with the FFMA chain
// moved to packed fma.rn.f32x2. R14 proved the binding constraint is
// FMA/ALU issue count, not MUFU. R4's f32x2 spill is obsolete: regs are at
// 72 post-R13, and coefficients are stored pair-interleaved in global so
// packed u64 loads REPLACE scalar ones at identical register cost (40).
// FMA-class issues per pair-row: ~56 -> ~30. Exp stays scalar ex2.f32
// (R14 showed f16x2 exp is speed-neutral; scalar keeps rel_err ~7e-8).
// ---------------------------------------------------------------------------

#define LOG2E_F    1.4426950408889634f
#define LN2_F      0.6931471805599453f
#define LOG2_2PI_F 2.6514961294723187f   // log2(2*pi)

constexpr int PF   = 512;   // features
constexpr int PP   = 256;   // scope pairs
constexpr int PM   = 8;     // mixture components
constexpr int ROWS = 8;     // batch rows per chunk

// Packed coefficients: [j in 0..4][q in 0..3][p], each u64 = (m=2q, m=2q+1).
__device__ unsigned long long g_coefp[5 * 4 * PP];
__device__ int2 g_scope2[PP];          // per-pair (s0, s1)

__device__ __forceinline__ float ex2f(float v) {
    float r; asm("ex2.approx.ftz.f32 %0, %1;" : "=f"(r) : "f"(v)); return r;
}
__device__ __forceinline__ float lg2f(float v) {
    float r; asm("lg2.approx.ftz.f32 %0, %1;" : "=f"(r) : "f"(v)); return r;
}
__device__ __forceinline__ float rcpf(float v) {
    float r; asm("rcp.approx.ftz.f32 %0, %1;" : "=f"(r) : "f"(v)); return r;
}
// --- packed f32x2 helpers (Blackwell FFMA2/FADD2/FMUL2 via PTX) ------------
__device__ __forceinline__ unsigned long long pk2(float lo, float hi) {
    unsigned long long d;
    asm("mov.b64 %0, {%1, %2};" : "=l"(d) : "f"(lo), "f"(hi));
    return d;
}
__device__ __forceinline__ void upk2(float& lo, float& hi, unsigned long long v) {
    asm("mov.b64 {%0, %1}, %2;" : "=f"(lo), "=f"(hi) : "l"(v));
}
__device__ __forceinline__ unsigned long long fma2(unsigned long long a,
                                                   unsigned long long b,
                                                   unsigned long long c) {
    unsigned long long d;
    asm("fma.rn.f32x2 %0, %1, %2, %3;" : "=l"(d) : "l"(a), "l"(b), "l"(c));
    return d;
}
__device__ __forceinline__ unsigned long long add2(unsigned long long a,
                                                   unsigned long long b) {
    unsigned long long d;
    asm("add.rn.f32x2 %0, %1, %2;" : "=l"(d) : "l"(a), "l"(b));
    return d;
}
__device__ __forceinline__ unsigned long long mul2(unsigned long long a,
                                                   unsigned long long b) {
    unsigned long long d;
    asm("mul.rn.f32x2 %0, %1, %2;" : "=l"(d) : "l"(a), "l"(b));
    return d;
}
__device__ __forceinline__ void cp16(uint32_t smem_dst, const void* gmem_src) {
    asm volatile("cp.async.cg.shared.global [%0], [%1], 16;\n"
                 :: "r"(smem_dst), "l"(gmem_src));
}
__device__ __forceinline__ void cp_commit() {
    asm volatile("cp.async.commit_group;\n" ::: "memory");
}
template <int N>
__device__ __forceinline__ void cp_wait() {
    asm volatile("cp.async.wait_group %0;\n" :: "n"(N) : "memory");
}

// ---------------------------------------------------------------------------
// Precompute: 256 blocks x 32 threads. Block p = scope pair p; lane m < 8
// computes component m's 5 coefficients, written pair-interleaved.
// ---------------------------------------------------------------------------
__global__ void spn_precompute_kernel(const float* __restrict__ mean,
                                      const float* __restrict__ stdv,
                                      const float* __restrict__ wts,
                                      const int*   __restrict__ w32)
{
    const int p    = blockIdx.x;
    const int lane = threadIdx.x;

    // dtype detection: int64 LE values in [0,512) have zero odd words; an
    // int32 permutation of 0..511 has at most ONE zero among words 1..63.
    unsigned odd = __ballot_sync(0xffffffffu, w32[2 * lane + 1] != 0);
    const bool is32 = (odd != 0);

    if (lane == 0) {
        int s0 = (is32 ? w32[2 * p] : w32[4 * p]) & (PF - 1);
        int s1 = (is32 ? w32[2 * p + 1] : w32[4 * p + 2]) & (PF - 1);
        g_scope2[p] = make_int2(s0, s1);
    }

    // weight sum across the 8 components (xor offsets 4,2,1 reduce within
    // 8-lane groups, so lanes 0..7 all hold the sum of lanes 0..7)
    float w = (lane < PM) ? wts[p * PM + lane] : 0.f;
    float wsum = w;
    #pragma unroll
    for (int off = 4; off; off >>= 1)
        wsum += __shfl_xor_sync(0xffffffffu, wsum, off);

    if (lane >= PM) return;
    const int m = lane;
    const int q = m >> 1;
    const int h = m & 1;
    const float l2wsum = lg2f(wsum);

    int base = (p * PM + m) * 2;
    float mu1 = mean[base + 0], mu2 = mean[base + 1];
    float sd1 = stdv[base + 0], sd2 = stdv[base + 1];
    float r1 = rcpf(sd1), r2 = rcpf(sd2);
    float i1 = r1 * r1, i2 = r2 * r2;

    float* gc = (float*)g_coefp;   // halves of the packed u64s
    gc[((0 * 4 + q) * PP + p) * 2 + h] = -0.5f * i1 * LOG2E_F;   // A1
    gc[((1 * 4 + q) * PP + p) * 2 + h] =  mu1  * i1 * LOG2E_F;   // B1
    gc[((2 * 4 + q) * PP + p) * 2 + h] = -0.5f * i2 * LOG2E_F;   // A2
    gc[((3 * 4 + q) * PP + p) * 2 + h] =  mu2  * i2 * LOG2E_F;   // B2
    gc[((4 * 4 + q) * PP + p) * 2 + h] =                          // C
        -0.5f * LOG2E_F * (mu1 * mu1 * i1 + mu2 * mu2 * i2)
        - lg2f(sd1 * sd2) - LOG2_2PI_F + lg2f(w) - l2wsum;
}

// ---------------------------------------------------------------------------
// Main kernel: blockDim = 256 (thread == pair). Grid-stride over 8-row
// chunks, double-buffered cp.async, packed-f32x2 quadratic, transposed
// smem reduction.
// ---------------------------------------------------------------------------
__global__ __launch_bounds__(256, 3)
void spn_main_kernel(const float* __restrict__ x,
                     float* __restrict__ out,
                     int nchunks)
{
    __shared__ float sx[2][ROWS][PF];
    __shared__ float sred[ROWS][PP];   // [row][pair] transpose buffer

    const int tid  = threadIdx.x;
    const int lane = tid & 31;
    const int warp = tid >> 5;

    // Packed coefficients -> registers (u64 loads, lane stride 8B; 40 regs —
    // identical footprint to the scalar version's 40 floats)
    unsigned long long A1p[4], B1p[4], A2p[4], B2p[4], Cp[4];
    #pragma unroll
    for (int q = 0; q < 4; q++) {
        A1p[q] = g_coefp[(0 * 4 + q) * PP + tid];
        B1p[q] = g_coefp[(1 * 4 + q) * PP + tid];
        A2p[q] = g_coefp[(2 * 4 + q) * PP + tid];
        B2p[q] = g_coefp[(3 * 4 + q) * PP + tid];
        Cp [q] = g_coefp[(4 * 4 + q) * PP + tid];
    }
    const int2 ss = g_scope2[tid];
    const int s0 = ss.x, s1 = ss.y;

    const int stride = gridDim.x;
    const uint32_t sbase = (uint32_t)__cvta_generic_to_shared(&sx[0][0][0]);

    // Prologue: stage first chunk into buffer 0.
    int c = blockIdx.x;
    if (c < nchunks) {
        const char* src = (const char*)(x + (size_t)c * ROWS * PF);
        #pragma unroll
        for (int k = 0; k < 4; k++)
            cp16(sbase + (tid + k * 256) * 16, src + (tid + k * 256) * 16);
    }
    cp_commit();

    int buf = 0;
    for (; c < nchunks; c += stride, buf ^= 1) {
        int cn = c + stride;
        if (cn < nchunks) {
            const char* src = (const char*)(x + (size_t)cn * ROWS * PF);
            uint32_t dst = sbase + (uint32_t)(buf ^ 1) * (ROWS * PF * 4);
            #pragma unroll
            for (int k = 0; k < 4; k++)
                cp16(dst + (tid + k * 256) * 16, src + (tid + k * 256) * 16);
        }
        cp_commit();
        cp_wait<1>();          // current chunk's group has landed
        __syncthreads();       // visible to all; prev iter's sred consumed

        #pragma unroll
        for (int r = 0; r < ROWS; r++) {
            float x1 = sx[buf][r][s0];
            float x2 = sx[buf][r][s1];

            // squares via one packed mul
            unsigned long long xp  = pk2(x1, x2);
            unsigned long long xsp = mul2(xp, xp);
            float x1s, x2s; upk2(x1s, x2s, xsp);

            unsigned long long x1b  = pk2(x1,  x1);
            unsigned long long x2b  = pk2(x2,  x2);
            unsigned long long x1sb = pk2(x1s, x1s);
            unsigned long long x2sb = pk2(x2s, x2s);

            // t = A1*x1s + B1*x1 + A2*x2s + B2*x2 + C   (4 FFMA2 per q-pair)
            float t[PM];
            unsigned long long tp[4];
            #pragma unroll
            for (int q = 0; q < 4; q++) {
                unsigned long long v = fma2(B2p[q], x2b, Cp[q]);
                v = fma2(A2p[q], x2sb, v);
                v = fma2(B1p[q], x1b, v);
                v = fma2(A1p[q], x1sb, v);
                tp[q] = v;
                upk2(t[2 * q], t[2 * q + 1], v);   // register-pair aliasing
            }
            float m01 = fmaxf(t[0], t[1]), m23 = fmaxf(t[2], t[3]);
            float m45 = fmaxf(t[4], t[5]), m67 = fmaxf(t[6], t[7]);
            float mx  = fmaxf(fmaxf(m01, m23), fmaxf(m45, m67));

            // subs via 4 packed adds; exp stays scalar f32 (precision + R14
            // showed packed exp is speed-neutral)
            unsigned long long mxn = pk2(-mx, -mx);
            float e0, e1, e2, e3, e4, e5, e6, e7;
            upk2(e0, e1, add2(tp[0], mxn));
            upk2(e2, e3, add2(tp[1], mxn));
            upk2(e4, e5, add2(tp[2], mxn));
            upk2(e6, e7, add2(tp[3], mxn));
            float s = ((ex2f(e0) + ex2f(e1)) + (ex2f(e2) + ex2f(e3)))
                    + ((ex2f(e4) + ex2f(e5)) + (ex2f(e6) + ex2f(e7)));

            // transpose store: lanes hit distinct banks (addr = r*256 + tid)
            sred[r][tid] = mx + lg2f(s);
        }
        __syncthreads();

        // Warp w sums row w over all 256 pairs: 8 stride-32 loads
        // (conflict-free) + tree add + 5-level shuffle. Uniform across warps.
        {
            float v0 = sred[warp][lane +   0] + sred[warp][lane +  32];
            float v1 = sred[warp][lane +  64] + sred[warp][lane +  96];
            float v2 = sred[warp][lane + 128] + sred[warp][lane + 160];
            float v3 = sred[warp][lane + 192] + sred[warp][lane + 224];
            float v  = (v0 + v1) + (v2 + v3);
            #pragma unroll
            for (int off = 16; off; off >>= 1)
                v += __shfl_xor_sync(0xffffffffu, v, off);
            if (lane == 0) out[c * ROWS + warp] = v * LN2_F;
        }
        // No trailing barrier: next iter's top barrier (after cp_wait) orders
        // this iter's sred reads against next iter's sred writes, and the
        // cp.async issued at next-iter top targets the buffer whose last
        // reads were sealed by this iteration's mid barrier.
    }
}

// ---------------------------------------------------------------------------
// Launch. Inputs: x f32[32768*512], mean f32[256*8*2], std f32[256*8*2],
// weights f32[256*8], scopes int{32,64}[512]. Output f32[32768].
// ---------------------------------------------------------------------------
extern "C" void kernel_launch(void* const* d_in, const int* in_sizes, int n_in,
                              void* d_out, int out_size)
{
    const float* x      = (const float*)d_in[0];
    const float* mean   = (const float*)d_in[1];
    const float* stdv   = (const float*)d_in[2];
    const float* wts    = (const float*)d_in[3];
    const int*   w32    = (const int*)d_in[4];
    float*       out    = (float*)d_out;

    const int B = in_sizes[0] / PF;          // 32768
    const int nchunks = B / ROWS;            // 4096

    spn_precompute_kernel<<<PP, 32>>>(mean, stdv, wts, w32);

    // Grid 1184: measured-best main-loop config.
    int blocks = 1184;
    if (blocks > nchunks) blocks = nchunks;
    spn_main_kernel<<<blocks, 256>>>(x, out, nchunks);
}